// round 13
// baseline (speedup 1.0000x reference)
#include <cuda_runtime.h>
#include <cuda_fp16.h>
#include <cstdint>

// Problem constants
#define B_DIM   8192
#define IN_DIM  1024
#define OUT_DIM 1024
#define ORD     8              // ORDER+1 powers per input
#define KTOT    (IN_DIM * ORD) // 8192 reduction length

#define BM 128
#define BN 128
#define BK 32                  // 4 inputs * 8 powers per K-tile
#define NKT (KTOT / BK)        // 256 K-tiles
#define NBM (B_DIM / BM)       // 64
#define NBN (OUT_DIM / BN)     // 8

#define STAGES 3
#define TILE_U4 512            // 8 KB per operand tile = 512 uint4

// Precomputed smem-image scratch
//   gA_img[bm][kt] = 8 KB A-tile image (quad-swizzled fp16 powers)   -> 128 MB
//   gB_img[bn][kt] = 8 KB B-tile image (xor-swizzled k-paired half2) ->  16 MB
__device__ __align__(16) uint4 gA_img[(size_t)NBM * NKT * TILE_U4];
__device__ __align__(16) uint4 gB_img[(size_t)NBN * NKT * TILE_U4];

// ---------------------------------------------------------------------------
// Helpers
// ---------------------------------------------------------------------------
__device__ __forceinline__ uint32_t smem_u32(const void* p) {
    uint32_t a;
    asm("{ .reg .u64 t; cvta.to.shared.u64 t, %1; cvt.u32.u64 %0, t; }"
        : "=r"(a) : "l"(p));
    return a;
}
__device__ __forceinline__ uint32_t packh2(float lo, float hi) {
    __half2 h = __floats2half2_rn(lo, hi);
    return *reinterpret_cast<uint32_t*>(&h);
}
__device__ __forceinline__ float tanh_fast(float x) {
    float r;
    asm("tanh.approx.f32 %0, %1;" : "=f"(r) : "f"(x));
    return r;
}
__device__ __forceinline__ void ldsm4(uint32_t* f, uint32_t addr) {
    asm volatile("ldmatrix.sync.aligned.m8n8.x4.shared.b16 {%0,%1,%2,%3}, [%4];"
                 : "=r"(f[0]), "=r"(f[1]), "=r"(f[2]), "=r"(f[3])
                 : "r"(addr) : "memory");
}
__device__ __forceinline__ void mma16816(float* c, const uint32_t* a,
                                         uint32_t b0, uint32_t b1) {
    asm("mma.sync.aligned.m16n8k16.row.col.f32.f16.f16.f32 "
        "{%0,%1,%2,%3}, {%4,%5,%6,%7}, {%8,%9}, {%0,%1,%2,%3};"
        : "+f"(c[0]), "+f"(c[1]), "+f"(c[2]), "+f"(c[3])
        : "r"(a[0]), "r"(a[1]), "r"(a[2]), "r"(a[3]), "r"(b0), "r"(b1));
}
__device__ __forceinline__ void cp16(uint32_t smaddr, const void* g) {
    asm volatile("cp.async.cg.shared.global [%0], [%1], 16;"
                 :: "r"(smaddr), "l"(g) : "memory");
}
__device__ __forceinline__ void cp_commit() {
    asm volatile("cp.async.commit_group;" ::: "memory");
}
__device__ __forceinline__ void cp_wait1() {
    asm volatile("cp.async.wait_group 1;" ::: "memory");
}
__device__ __forceinline__ void cp_wait0() {
    asm volatile("cp.async.wait_group 0;" ::: "memory");
}

// ---------------------------------------------------------------------------
// Prep kernel A: tanh + powers -> quad-swizzled fp16 tile image
//   image uint4 idx (in tile): row*4 + (q ^ ((row>>1)&3))
//   content: half2 pairs {1,t},{t2,t3},{t4,t5},{t6,t7} of t = tanh(x*r)
// ---------------------------------------------------------------------------
__global__ void prep_a_kernel(const float* __restrict__ x,
                              const float* __restrict__ rp) {
    const float r = *rp;
    const int kt = blockIdx.x;
    const int bm = blockIdx.y;
    const int tid = threadIdx.x;
    const int row = tid >> 2;
    const int q   = tid & 3;

    const float xv = x[(size_t)(bm * BM + row) * IN_DIM + kt * 4 + q];
    const float t  = tanh_fast(xv * r);
    const float t2 = t * t, t3 = t2 * t, t4 = t2 * t2;
    const float t5 = t4 * t, t6 = t3 * t3, t7 = t4 * t3;

    uint4 qv;
    qv.x = packh2(1.f, t);  qv.y = packh2(t2, t3);
    qv.z = packh2(t4, t5);  qv.w = packh2(t6, t7);

    gA_img[((size_t)bm * NKT + kt) * TILE_U4 + row * 4 + (q ^ ((row >> 1) & 3))] = qv;
}

// ---------------------------------------------------------------------------
// Prep kernel B: coef -> xor-swizzled k-paired half2 tile image
//   word idx (in tile): q0*128 + (j ^ ((q0&3)<<3)), q0 = k-pair index 0..15
//   content: half2(coef[j][kt*32+2*q0], coef[j][kt*32+2*q0+1])
// ---------------------------------------------------------------------------
__global__ void prep_b_kernel(const float* __restrict__ coef) {
    const int kt = blockIdx.x;
    const int bn = blockIdx.y;
    const int tid = threadIdx.x;
    const int s = tid & 3;        // k-octet slot (8 floats)
    const int j = tid >> 2;       // column 0..127

    const float* cp = &coef[(size_t)(bn * BN + j) * KTOT + kt * BK + s * 8];
    const float4 c0 = *reinterpret_cast<const float4*>(cp);
    const float4 c1 = *reinterpret_cast<const float4*>(cp + 4);

    uint32_t* gw = reinterpret_cast<uint32_t*>(
        &gB_img[((size_t)bn * NKT + kt) * TILE_U4]);
    const int q0 = s * 4;         // q0&3 == u for u = 0..3
    gw[(q0 + 0) * 128 + (j ^ 0)]  = packh2(c0.x, c0.y);
    gw[(q0 + 1) * 128 + (j ^ 8)]  = packh2(c0.z, c0.w);
    gw[(q0 + 2) * 128 + (j ^ 16)] = packh2(c1.x, c1.y);
    gw[(q0 + 3) * 128 + (j ^ 24)] = packh2(c1.z, c1.w);
}

// ---------------------------------------------------------------------------
// GEMM kernel: 3-stage cp.async fp16 m16n8k16 pipeline (exact R9 structure),
// occupancy raised 2 -> 3 (the single change this round).
// 128 threads = 4 warps, 2x2 over the 128x128 block tile, 64x64 per warp.
// smem stage layout: [A tile 8KB][B tile 8KB]; 3 stages = 48 KB static.
// ---------------------------------------------------------------------------
__global__ __launch_bounds__(128, 3)
void taylor_pipe_kernel(float* __restrict__ out) {
    __shared__ __align__(16) uint4 smem[STAGES][2 * TILE_U4];

    const int tid  = threadIdx.x;
    const int lane = tid & 31;
    const int warp = tid >> 5;
    const int warp_m = warp >> 1;   // 2 warps over M (64 rows each)
    const int warp_n = warp & 1;    // 2 warps over N (64 cols each)
    const int gid = lane >> 2;
    const int tig = lane & 3;

    const int bn = blockIdx.x;
    const int bm = blockIdx.y;

    const uint4* gA = &gA_img[(size_t)bm * NKT * TILE_U4 + tid * 4];
    const uint4* gB = &gB_img[(size_t)bn * NKT * TILE_U4 + tid * 4];

    const uint32_t sBase = smem_u32(&smem[0][0]);
    // per-thread smem targets within a stage (contiguous across threads)
    const uint32_t smA_off = (uint32_t)(tid * 64);
    const uint32_t smB_off = (uint32_t)(8192 + tid * 64);

    // ldmatrix lane geometry (A consumer)
    const int lrow = lane & 15;
    const int lkc  = lane >> 4;
    const int lsw  = (lrow >> 1) & 3;

    float acc[4][8][4];
#pragma unroll
    for (int mt = 0; mt < 4; mt++)
#pragma unroll
        for (int nt = 0; nt < 8; nt++)
#pragma unroll
            for (int c = 0; c < 4; c++) acc[mt][nt][c] = 0.f;

    auto issue = [&](int kt, int stage) {
        const uint32_t sa = sBase + stage * 16384 + smA_off;
        const uint32_t sb = sBase + stage * 16384 + smB_off;
        const uint4* ga = gA + (size_t)kt * TILE_U4;
        const uint4* gb = gB + (size_t)kt * TILE_U4;
#pragma unroll
        for (int u = 0; u < 4; u++) {
            cp16(sa + u * 16, ga + u);
            cp16(sb + u * 16, gb + u);
        }
        cp_commit();
    };

    // prologue: fill 2 stages
    issue(0, 0);
    issue(1, 1);

#pragma unroll 1
    for (int kt = 0; kt < NKT; ++kt) {
        const int stage = kt % STAGES;

        // Drain the group carrying tile kt. Steady state: two groups
        // outstanding -> wait_group 1. Final iteration: only one left ->
        // wait_group 0 (wait_group 1 would consume a stale tile).
        if (kt == NKT - 1) cp_wait0(); else cp_wait1();
        __syncthreads();

        const uint32_t aBase = sBase + stage * 16384;
        const uint32_t* sBw = reinterpret_cast<const uint32_t*>(
            &smem[stage][TILE_U4]);

#pragma unroll
        for (int ks = 0; ks < 2; ++ks) {
            uint32_t af[4][4];
#pragma unroll
            for (int mt = 0; mt < 4; mt++) {
                const int row_g = warp_m * 64 + mt * 16 + lrow;
                const int qp = (ks * 2 + lkc) ^ lsw;
                ldsm4(af[mt], aBase + (uint32_t)(row_g * 64 + qp * 16));
            }
#pragma unroll
            for (int nt = 0; nt < 8; nt++) {
                const int col = warp_n * 64 + nt * 8 + gid;
                const int q0 = ks * 8 + tig;
                const int widx = q0 * 128 + (col ^ (tig << 3));
                const uint32_t b0 = sBw[widx];
                const uint32_t b1 = sBw[widx + 4 * 128];
#pragma unroll
                for (int mt = 0; mt < 4; mt++)
                    mma16816(acc[mt][nt], af[mt], b0, b1);
            }
        }

        // issue after the mma block (R9-validated position)
        if (kt + 2 < NKT) issue(kt + 2, (kt + 2) % STAGES);
    }

    // ---- epilogue: float2 stores ----
    const int bm0 = bm * BM, bn0 = bn * BN;
#pragma unroll
    for (int mt = 0; mt < 4; mt++) {
        const int row = bm0 + warp_m * 64 + mt * 16 + gid;
#pragma unroll
        for (int nt = 0; nt < 8; nt++) {
            const int col = bn0 + warp_n * 64 + nt * 8 + tig * 2;
            *reinterpret_cast<float2*>(&out[(size_t)row * OUT_DIM + col]) =
                make_float2(acc[mt][nt][0], acc[mt][nt][1]);
            *reinterpret_cast<float2*>(&out[(size_t)(row + 8) * OUT_DIM + col]) =
                make_float2(acc[mt][nt][2], acc[mt][nt][3]);
        }
    }
}

// ---------------------------------------------------------------------------
// Launch
// ---------------------------------------------------------------------------
extern "C" void kernel_launch(void* const* d_in, const int* in_sizes, int n_in,
                              void* d_out, int out_size) {
    const float* x    = (const float*)d_in[0];   // [8192, 1024] f32
    const float* rng  = (const float*)d_in[1];   // scalar f32
    const float* coef = (const float*)d_in[2];   // [1024, 1024, 8] f32
    float* out        = (float*)d_out;           // [8192, 1024] f32

    (void)in_sizes; (void)n_in; (void)out_size;

    // 1) prep A-tile images (tanh + powers, fp16, swizzled)
    {
        dim3 grid(NKT, NBM);   // (256, 64)
        prep_a_kernel<<<grid, 512>>>(x, rng);
    }
    // 2) prep B-tile images (coef -> fp16 k-paired, swizzled)
    {
        dim3 grid(NKT, NBN);   // (256, 8)
        prep_b_kernel<<<grid, 512>>>(coef);
    }
    // 3) pipelined fp16 tensor-core GEMM (4 warps, 64x64 warp tiles, occ 3)
    {
        dim3 grid(NBN, NBM);   // (8, 64)
        taylor_pipe_kernel<<<grid, 128>>>(out);
    }
}

// round 16
// speedup vs baseline: 1.0133x; 1.0133x over previous
#include <cuda_runtime.h>
#include <cuda_fp16.h>
#include <cstdint>

// Problem constants
#define B_DIM   8192
#define IN_DIM  1024
#define OUT_DIM 1024
#define ORD     8              // ORDER+1 powers per input
#define KTOT    (IN_DIM * ORD) // 8192 reduction length

#define BM 128
#define BN 128
#define BK 32                  // 4 inputs * 8 powers per base tile
#define NKT (KTOT / BK)        // 256 base K-tiles
#define NST (NKT / 2)          // 128 supertiles (BK=64)
#define NBM (B_DIM / BM)       // 64
#define NBN (OUT_DIM / BN)     // 8

#define TILE_U4 512            // 8 KB per base tile = 512 uint4
#define STG_BYTES 32768        // stage = [A0 8K][A1 8K][B0 8K][B1 8K]
#define SMEM_GEMM (3 * STG_BYTES)   // 96 KB dynamic, 3 stages

// Precomputed smem-image scratch
//   gA_img[bm][kt] = 8 KB A-tile image (quad-swizzled fp16 powers)   -> 128 MB
//   gB_img[bn][kt] = 8 KB B-tile image (xor-swizzled k-paired half2) ->  16 MB
__device__ __align__(16) uint4 gA_img[(size_t)NBM * NKT * TILE_U4];
__device__ __align__(16) uint4 gB_img[(size_t)NBN * NKT * TILE_U4];

// ---------------------------------------------------------------------------
// Helpers
// ---------------------------------------------------------------------------
__device__ __forceinline__ uint32_t smem_u32(const void* p) {
    uint32_t a;
    asm("{ .reg .u64 t; cvta.to.shared.u64 t, %1; cvt.u32.u64 %0, t; }"
        : "=r"(a) : "l"(p));
    return a;
}
__device__ __forceinline__ uint32_t packh2(float lo, float hi) {
    __half2 h = __floats2half2_rn(lo, hi);
    return *reinterpret_cast<uint32_t*>(&h);
}
__device__ __forceinline__ float tanh_fast(float x) {
    float r;
    asm("tanh.approx.f32 %0, %1;" : "=f"(r) : "f"(x));
    return r;
}
__device__ __forceinline__ void ldsm4(uint32_t* f, uint32_t addr) {
    asm volatile("ldmatrix.sync.aligned.m8n8.x4.shared.b16 {%0,%1,%2,%3}, [%4];"
                 : "=r"(f[0]), "=r"(f[1]), "=r"(f[2]), "=r"(f[3])
                 : "r"(addr) : "memory");
}
__device__ __forceinline__ void mma16816(float* c, const uint32_t* a,
                                         uint32_t b0, uint32_t b1) {
    asm("mma.sync.aligned.m16n8k16.row.col.f32.f16.f16.f32 "
        "{%0,%1,%2,%3}, {%4,%5,%6,%7}, {%8,%9}, {%0,%1,%2,%3};"
        : "+f"(c[0]), "+f"(c[1]), "+f"(c[2]), "+f"(c[3])
        : "r"(a[0]), "r"(a[1]), "r"(a[2]), "r"(a[3]), "r"(b0), "r"(b1));
}
__device__ __forceinline__ void cp16(uint32_t smaddr, const void* g) {
    asm volatile("cp.async.cg.shared.global [%0], [%1], 16;"
                 :: "r"(smaddr), "l"(g) : "memory");
}
__device__ __forceinline__ void cp_commit() {
    asm volatile("cp.async.commit_group;" ::: "memory");
}
__device__ __forceinline__ void cp_wait1() {
    asm volatile("cp.async.wait_group 1;" ::: "memory");
}
__device__ __forceinline__ void cp_wait0() {
    asm volatile("cp.async.wait_group 0;" ::: "memory");
}

// ---------------------------------------------------------------------------
// Prep kernel A: tanh + powers -> quad-swizzled fp16 tile image
//   image uint4 idx (in tile): row*4 + (q ^ ((row>>1)&3))
//   content: half2 pairs {1,t},{t2,t3},{t4,t5},{t6,t7} of t = tanh(x*r)
// ---------------------------------------------------------------------------
__global__ void prep_a_kernel(const float* __restrict__ x,
                              const float* __restrict__ rp) {
    const float r = *rp;
    const int kt = blockIdx.x;
    const int bm = blockIdx.y;
    const int tid = threadIdx.x;
    const int row = tid >> 2;
    const int q   = tid & 3;

    const float xv = x[(size_t)(bm * BM + row) * IN_DIM + kt * 4 + q];
    const float t  = tanh_fast(xv * r);
    const float t2 = t * t, t3 = t2 * t, t4 = t2 * t2;
    const float t5 = t4 * t, t6 = t3 * t3, t7 = t4 * t3;

    uint4 qv;
    qv.x = packh2(1.f, t);  qv.y = packh2(t2, t3);
    qv.z = packh2(t4, t5);  qv.w = packh2(t6, t7);

    gA_img[((size_t)bm * NKT + kt) * TILE_U4 + row * 4 + (q ^ ((row >> 1) & 3))] = qv;
}

// ---------------------------------------------------------------------------
// Prep kernel B: coef -> xor-swizzled k-paired half2 tile image
//   word idx (in tile): q0*128 + (j ^ ((q0&3)<<3)), q0 = k-pair index 0..15
//   content: half2(coef[j][kt*32+2*q0], coef[j][kt*32+2*q0+1])
// ---------------------------------------------------------------------------
__global__ void prep_b_kernel(const float* __restrict__ coef) {
    const int kt = blockIdx.x;
    const int bn = blockIdx.y;
    const int tid = threadIdx.x;
    const int s = tid & 3;        // k-octet slot (8 floats)
    const int j = tid >> 2;       // column 0..127

    const float* cp = &coef[(size_t)(bn * BN + j) * KTOT + kt * BK + s * 8];
    const float4 c0 = *reinterpret_cast<const float4*>(cp);
    const float4 c1 = *reinterpret_cast<const float4*>(cp + 4);

    uint32_t* gw = reinterpret_cast<uint32_t*>(
        &gB_img[((size_t)bn * NKT + kt) * TILE_U4]);
    const int q0 = s * 4;         // q0&3 == u for u = 0..3
    gw[(q0 + 0) * 128 + (j ^ 0)]  = packh2(c0.x, c0.y);
    gw[(q0 + 1) * 128 + (j ^ 8)]  = packh2(c0.z, c0.w);
    gw[(q0 + 2) * 128 + (j ^ 16)] = packh2(c1.x, c1.y);
    gw[(q0 + 3) * 128 + (j ^ 24)] = packh2(c1.z, c1.w);
}

// ---------------------------------------------------------------------------
// GEMM kernel: 3-stage cp.async fp16 m16n8k16 pipeline, BK=64 supertiles.
// ONLY change vs R9 (387us): two base tiles per stage -> 128 iterations,
// half the barriers. Copy mapping per base tile is byte-identical to R9
// (thread -> tid*32 bytes, contiguous across threads; R11's tid*128-stride
// mapping was the regression there). Issue stays AFTER the mma block.
// 128 threads = 4 warps, 2x2 over 128x128, 64x64 per warp. 96 KB dyn smem.
// ---------------------------------------------------------------------------
__global__ __launch_bounds__(128, 2)
void taylor_pipe_kernel(float* __restrict__ out) {
    extern __shared__ __align__(16) uint4 smem[];

    const int tid  = threadIdx.x;
    const int lane = tid & 31;
    const int warp = tid >> 5;
    const int warp_m = warp >> 1;   // 2 warps over M (64 rows each)
    const int warp_n = warp & 1;    // 2 warps over N (64 cols each)
    const int gid = lane >> 2;
    const int tig = lane & 3;

    const int bn = blockIdx.x;
    const int bm = blockIdx.y;

    const uint4* gA = &gA_img[(size_t)bm * NKT * TILE_U4 + tid * 4];
    const uint4* gB = &gB_img[(size_t)bn * NKT * TILE_U4 + tid * 4];

    const uint32_t sBase = smem_u32(&smem[0]);
    const uint32_t thrOff = (uint32_t)(tid * 64);   // 2x16B per base tile

    // ldmatrix lane geometry (A consumer)
    const int lrow = lane & 15;
    const int lkc  = lane >> 4;
    const int lsw  = (lrow >> 1) & 3;

    float acc[4][8][4];
#pragma unroll
    for (int mt = 0; mt < 4; mt++)
#pragma unroll
        for (int nt = 0; nt < 8; nt++)
#pragma unroll
            for (int c = 0; c < 4; c++) acc[mt][nt][c] = 0.f;

    // Copy one supertile (base tiles 2st, 2st+1) into a stage.
    // Each base tile uses the R9 mapping exactly: A half h at stage+h*8192,
    // B half h at stage+16384+h*8192; thread writes 2 uint4 at thrOff.
    auto issue = [&](int st, int stage) {
        const uint32_t sbase = sBase + stage * STG_BYTES;
#pragma unroll
        for (int h = 0; h < 2; h++) {
            const int kt = st * 2 + h;
            const uint32_t sa = sbase + h * 8192 + thrOff;
            const uint32_t sb = sbase + 16384 + h * 8192 + thrOff;
            const uint4* ga = gA + (size_t)kt * TILE_U4;
            const uint4* gb = gB + (size_t)kt * TILE_U4;
#pragma unroll
            for (int u = 0; u < 4; u++) {
                cp16(sa + u * 16, ga + u);
                cp16(sb + u * 16, gb + u);
            }
        }
        cp_commit();
    };

    // prologue: fill 2 stages
    issue(0, 0);
    issue(1, 1);

#pragma unroll 1
    for (int st = 0; st < NST; ++st) {
        const int stage = st % 3;

        // Steady state: groups {st, st+1} outstanding -> wait_group 1 drains
        // st. Final iteration: only {st} -> wait_group 0 (wait_group 1 would
        // consume a stale tile; R7 bug class).
        if (st == NST - 1) cp_wait0(); else cp_wait1();
        __syncthreads();

        const uint32_t stg = sBase + stage * STG_BYTES;
        const uint32_t* sBw = reinterpret_cast<const uint32_t*>(
            reinterpret_cast<const char*>(smem) + stage * STG_BYTES + 16384);

#pragma unroll
        for (int ks = 0; ks < 4; ++ks) {
            const int k   = ks >> 1;   // base tile within supertile
            const int ksl = ks & 1;    // k16-step within base tile

            uint32_t af[4][4];
#pragma unroll
            for (int mt = 0; mt < 4; mt++) {
                const int row_g = warp_m * 64 + mt * 16 + lrow;
                const int qp = (ksl * 2 + lkc) ^ lsw;
                ldsm4(af[mt], stg + (uint32_t)(k * 8192 + row_g * 64 + qp * 16));
            }
#pragma unroll
            for (int nt = 0; nt < 8; nt++) {
                const int col = warp_n * 64 + nt * 8 + gid;
                const int q0 = ksl * 8 + tig;
                const int widx = k * 2048 + q0 * 128 + (col ^ (tig << 3));
                const uint32_t b0 = sBw[widx];
                const uint32_t b1 = sBw[widx + 4 * 128];
#pragma unroll
                for (int mt = 0; mt < 4; mt++)
                    mma16816(acc[mt][nt], af[mt], b0, b1);
            }
        }

        // issue after the mma block (R9/R12-validated position)
        if (st + 2 < NST) issue(st + 2, (st + 2) % 3);
    }

    // ---- epilogue: float2 stores ----
    const int bm0 = bm * BM, bn0 = bn * BN;
#pragma unroll
    for (int mt = 0; mt < 4; mt++) {
        const int row = bm0 + warp_m * 64 + mt * 16 + gid;
#pragma unroll
        for (int nt = 0; nt < 8; nt++) {
            const int col = bn0 + warp_n * 64 + nt * 8 + tig * 2;
            *reinterpret_cast<float2*>(&out[(size_t)row * OUT_DIM + col]) =
                make_float2(acc[mt][nt][0], acc[mt][nt][1]);
            *reinterpret_cast<float2*>(&out[(size_t)(row + 8) * OUT_DIM + col]) =
                make_float2(acc[mt][nt][2], acc[mt][nt][3]);
        }
    }
}

// ---------------------------------------------------------------------------
// Launch
// ---------------------------------------------------------------------------
extern "C" void kernel_launch(void* const* d_in, const int* in_sizes, int n_in,
                              void* d_out, int out_size) {
    const float* x    = (const float*)d_in[0];   // [8192, 1024] f32
    const float* rng  = (const float*)d_in[1];   // scalar f32
    const float* coef = (const float*)d_in[2];   // [1024, 1024, 8] f32
    float* out        = (float*)d_out;           // [8192, 1024] f32

    (void)in_sizes; (void)n_in; (void)out_size;

    // 1) prep A-tile images (tanh + powers, fp16, swizzled)
    {
        dim3 grid(NKT, NBM);   // (256, 64)
        prep_a_kernel<<<grid, 512>>>(x, rng);
    }
    // 2) prep B-tile images (coef -> fp16 k-paired, swizzled)
    {
        dim3 grid(NKT, NBN);   // (256, 8)
        prep_b_kernel<<<grid, 512>>>(coef);
    }
    // 3) pipelined fp16 tensor-core GEMM (BK=64, R9 copy mapping, 96 KB smem)
    {
        cudaFuncSetAttribute(taylor_pipe_kernel,
                             cudaFuncAttributeMaxDynamicSharedMemorySize,
                             SMEM_GEMM);
        dim3 grid(NBN, NBM);   // (8, 64)
        taylor_pipe_kernel<<<grid, 128, SMEM_GEMM>>>(out);
    }
}

// round 17
// speedup vs baseline: 1.3062x; 1.2891x over previous
#include <cuda_runtime.h>
#include <cuda_fp16.h>
#include <cstdint>

// Problem constants
#define B_DIM   8192
#define IN_DIM  1024
#define OUT_DIM 1024
#define ORD     8              // ORDER+1 powers per input
#define KTOT    (IN_DIM * ORD) // 8192 reduction length

#define BM 128
#define BN 128
#define BK 32                  // 4 inputs * 8 powers per K-tile
#define NKT (KTOT / BK)        // 256 K-tiles
#define NBM (B_DIM / BM)       // 64
#define NBN (OUT_DIM / BN)     // 8

#define KSPLIT 4
#define NKT_PER (NKT / KSPLIT) // 64 K-tiles per CTA

#define STAGES 3
#define TILE_U4 512            // 8 KB per operand tile = 512 uint4

// Precomputed smem-image scratch
//   gA_img[bm][kt] = 8 KB A-tile image (quad-swizzled fp16 powers)   -> 128 MB
//   gB_img[bn][kt] = 8 KB B-tile image (xor-swizzled k-paired half2) ->  16 MB
__device__ __align__(16) uint4 gA_img[(size_t)NBM * NKT * TILE_U4];
__device__ __align__(16) uint4 gB_img[(size_t)NBN * NKT * TILE_U4];

// Split-K partial sums: gPart[z][b][j], 4 x 32 MB = 128 MB
__device__ __align__(16) float gPart[(size_t)KSPLIT * B_DIM * OUT_DIM];

// ---------------------------------------------------------------------------
// Helpers
// ---------------------------------------------------------------------------
__device__ __forceinline__ uint32_t smem_u32(const void* p) {
    uint32_t a;
    asm("{ .reg .u64 t; cvta.to.shared.u64 t, %1; cvt.u32.u64 %0, t; }"
        : "=r"(a) : "l"(p));
    return a;
}
__device__ __forceinline__ uint32_t packh2(float lo, float hi) {
    __half2 h = __floats2half2_rn(lo, hi);
    return *reinterpret_cast<uint32_t*>(&h);
}
__device__ __forceinline__ float tanh_fast(float x) {
    float r;
    asm("tanh.approx.f32 %0, %1;" : "=f"(r) : "f"(x));
    return r;
}
__device__ __forceinline__ void ldsm4(uint32_t* f, uint32_t addr) {
    asm volatile("ldmatrix.sync.aligned.m8n8.x4.shared.b16 {%0,%1,%2,%3}, [%4];"
                 : "=r"(f[0]), "=r"(f[1]), "=r"(f[2]), "=r"(f[3])
                 : "r"(addr) : "memory");
}
__device__ __forceinline__ void mma16816(float* c, const uint32_t* a,
                                         uint32_t b0, uint32_t b1) {
    asm("mma.sync.aligned.m16n8k16.row.col.f32.f16.f16.f32 "
        "{%0,%1,%2,%3}, {%4,%5,%6,%7}, {%8,%9}, {%0,%1,%2,%3};"
        : "+f"(c[0]), "+f"(c[1]), "+f"(c[2]), "+f"(c[3])
        : "r"(a[0]), "r"(a[1]), "r"(a[2]), "r"(a[3]), "r"(b0), "r"(b1));
}
__device__ __forceinline__ void cp16(uint32_t smaddr, const void* g) {
    asm volatile("cp.async.cg.shared.global [%0], [%1], 16;"
                 :: "r"(smaddr), "l"(g) : "memory");
}
__device__ __forceinline__ void cp_commit() {
    asm volatile("cp.async.commit_group;" ::: "memory");
}
__device__ __forceinline__ void cp_wait1() {
    asm volatile("cp.async.wait_group 1;" ::: "memory");
}
__device__ __forceinline__ void cp_wait0() {
    asm volatile("cp.async.wait_group 0;" ::: "memory");
}

// ---------------------------------------------------------------------------
// Prep kernel A: tanh + powers -> quad-swizzled fp16 tile image
//   image uint4 idx (in tile): row*4 + (q ^ ((row>>1)&3))
//   content: half2 pairs {1,t},{t2,t3},{t4,t5},{t6,t7} of t = tanh(x*r)
// ---------------------------------------------------------------------------
__global__ void prep_a_kernel(const float* __restrict__ x,
                              const float* __restrict__ rp) {
    const float r = *rp;
    const int kt = blockIdx.x;
    const int bm = blockIdx.y;
    const int tid = threadIdx.x;
    const int row = tid >> 2;
    const int q   = tid & 3;

    const float xv = x[(size_t)(bm * BM + row) * IN_DIM + kt * 4 + q];
    const float t  = tanh_fast(xv * r);
    const float t2 = t * t, t3 = t2 * t, t4 = t2 * t2;
    const float t5 = t4 * t, t6 = t3 * t3, t7 = t4 * t3;

    uint4 qv;
    qv.x = packh2(1.f, t);  qv.y = packh2(t2, t3);
    qv.z = packh2(t4, t5);  qv.w = packh2(t6, t7);

    gA_img[((size_t)bm * NKT + kt) * TILE_U4 + row * 4 + (q ^ ((row >> 1) & 3))] = qv;
}

// ---------------------------------------------------------------------------
// Prep kernel B: coef -> xor-swizzled k-paired half2 tile image
//   word idx (in tile): q0*128 + (j ^ ((q0&3)<<3)), q0 = k-pair index 0..15
//   content: half2(coef[j][kt*32+2*q0], coef[j][kt*32+2*q0+1])
// ---------------------------------------------------------------------------
__global__ void prep_b_kernel(const float* __restrict__ coef) {
    const int kt = blockIdx.x;
    const int bn = blockIdx.y;
    const int tid = threadIdx.x;
    const int s = tid & 3;        // k-octet slot (8 floats)
    const int j = tid >> 2;       // column 0..127

    const float* cp = &coef[(size_t)(bn * BN + j) * KTOT + kt * BK + s * 8];
    const float4 c0 = *reinterpret_cast<const float4*>(cp);
    const float4 c1 = *reinterpret_cast<const float4*>(cp + 4);

    uint32_t* gw = reinterpret_cast<uint32_t*>(
        &gB_img[((size_t)bn * NKT + kt) * TILE_U4]);
    const int q0 = s * 4;         // q0&3 == u for u = 0..3
    gw[(q0 + 0) * 128 + (j ^ 0)]  = packh2(c0.x, c0.y);
    gw[(q0 + 1) * 128 + (j ^ 8)]  = packh2(c0.z, c0.w);
    gw[(q0 + 2) * 128 + (j ^ 16)] = packh2(c1.x, c1.y);
    gw[(q0 + 3) * 128 + (j ^ 24)] = packh2(c1.z, c1.w);
}

// ---------------------------------------------------------------------------
// GEMM kernel: 3-stage cp.async fp16 m16n8k16 pipeline (exact R9 structure),
// split-K=4: blockIdx.z selects 64 of 256 K-tiles; partials to gPart[z].
// 128 threads = 4 warps, 2x2 over the 128x128 block tile, 64x64 per warp.
// smem stage layout: [A tile 8KB][B tile 8KB]; 3 stages = 48 KB static.
// ---------------------------------------------------------------------------
__global__ __launch_bounds__(128, 2)
void taylor_pipe_kernel() {
    __shared__ __align__(16) uint4 smem[STAGES][2 * TILE_U4];

    const int tid  = threadIdx.x;
    const int lane = tid & 31;
    const int warp = tid >> 5;
    const int warp_m = warp >> 1;   // 2 warps over M (64 rows each)
    const int warp_n = warp & 1;    // 2 warps over N (64 cols each)
    const int gid = lane >> 2;
    const int tig = lane & 3;

    const int bn = blockIdx.x;
    const int bm = blockIdx.y;
    const int kz = blockIdx.z;
    const int kt0 = kz * NKT_PER;

    const uint4* gA = &gA_img[((size_t)bm * NKT + kt0) * TILE_U4 + tid * 4];
    const uint4* gB = &gB_img[((size_t)bn * NKT + kt0) * TILE_U4 + tid * 4];

    const uint32_t sBase = smem_u32(&smem[0][0]);
    // per-thread smem targets within a stage (contiguous across threads)
    const uint32_t smA_off = (uint32_t)(tid * 64);
    const uint32_t smB_off = (uint32_t)(8192 + tid * 64);

    // ldmatrix lane geometry (A consumer)
    const int lrow = lane & 15;
    const int lkc  = lane >> 4;
    const int lsw  = (lrow >> 1) & 3;

    float acc[4][8][4];
#pragma unroll
    for (int mt = 0; mt < 4; mt++)
#pragma unroll
        for (int nt = 0; nt < 8; nt++)
#pragma unroll
            for (int c = 0; c < 4; c++) acc[mt][nt][c] = 0.f;

    auto issue = [&](int kt, int stage) {
        const uint32_t sa = sBase + stage * 16384 + smA_off;
        const uint32_t sb = sBase + stage * 16384 + smB_off;
        const uint4* ga = gA + (size_t)kt * TILE_U4;
        const uint4* gb = gB + (size_t)kt * TILE_U4;
#pragma unroll
        for (int u = 0; u < 4; u++) {
            cp16(sa + u * 16, ga + u);
            cp16(sb + u * 16, gb + u);
        }
        cp_commit();
    };

    // prologue: fill 2 stages
    issue(0, 0);
    issue(1, 1);

#pragma unroll 1
    for (int kt = 0; kt < NKT_PER; ++kt) {
        const int stage = kt % STAGES;

        // Drain the group carrying tile kt. Steady state: two groups
        // outstanding -> wait_group 1. Final iteration: only one left ->
        // wait_group 0 (wait_group 1 would consume a stale tile).
        if (kt == NKT_PER - 1) cp_wait0(); else cp_wait1();
        __syncthreads();

        const uint32_t aBase = sBase + stage * 16384;
        const uint32_t* sBw = reinterpret_cast<const uint32_t*>(
            &smem[stage][TILE_U4]);

#pragma unroll
        for (int ks = 0; ks < 2; ++ks) {
            uint32_t af[4][4];
#pragma unroll
            for (int mt = 0; mt < 4; mt++) {
                const int row_g = warp_m * 64 + mt * 16 + lrow;
                const int qp = (ks * 2 + lkc) ^ lsw;
                ldsm4(af[mt], aBase + (uint32_t)(row_g * 64 + qp * 16));
            }
#pragma unroll
            for (int nt = 0; nt < 8; nt++) {
                const int col = warp_n * 64 + nt * 8 + gid;
                const int q0 = ks * 8 + tig;
                const int widx = q0 * 128 + (col ^ (tig << 3));
                const uint32_t b0 = sBw[widx];
                const uint32_t b1 = sBw[widx + 4 * 128];
#pragma unroll
                for (int mt = 0; mt < 4; mt++)
                    mma16816(acc[mt][nt], af[mt], b0, b1);
            }
        }

        // issue after the mma block (R9-validated position)
        if (kt + 2 < NKT_PER) issue(kt + 2, (kt + 2) % STAGES);
    }

    // ---- epilogue: float2 stores to this split's partial buffer ----
    float* pout = &gPart[(size_t)kz * B_DIM * OUT_DIM];
    const int bm0 = bm * BM, bn0 = bn * BN;
#pragma unroll
    for (int mt = 0; mt < 4; mt++) {
        const int row = bm0 + warp_m * 64 + mt * 16 + gid;
#pragma unroll
        for (int nt = 0; nt < 8; nt++) {
            const int col = bn0 + warp_n * 64 + nt * 8 + tig * 2;
            *reinterpret_cast<float2*>(&pout[(size_t)row * OUT_DIM + col]) =
                make_float2(acc[mt][nt][0], acc[mt][nt][1]);
            *reinterpret_cast<float2*>(&pout[(size_t)(row + 8) * OUT_DIM + col]) =
                make_float2(acc[mt][nt][2], acc[mt][nt][3]);
        }
    }
}

// ---------------------------------------------------------------------------
// Reduce kernel: out = sum_z gPart[z], float4 vectorized
// ---------------------------------------------------------------------------
#define N_F4 (B_DIM * OUT_DIM / 4)   // 2,097,152 float4s per partial

__global__ void reduce_kernel(float* __restrict__ out) {
    const int i = blockIdx.x * blockDim.x + threadIdx.x;
    if (i < N_F4) {
        const float4* p = reinterpret_cast<const float4*>(gPart);
        const float4 a = p[i];
        const float4 b = p[i + (size_t)N_F4];
        const float4 c = p[i + (size_t)2 * N_F4];
        const float4 d = p[i + (size_t)3 * N_F4];
        float4 r;
        r.x = (a.x + b.x) + (c.x + d.x);
        r.y = (a.y + b.y) + (c.y + d.y);
        r.z = (a.z + b.z) + (c.z + d.z);
        r.w = (a.w + b.w) + (c.w + d.w);
        reinterpret_cast<float4*>(out)[i] = r;
    }
}

// ---------------------------------------------------------------------------
// Launch
// ---------------------------------------------------------------------------
extern "C" void kernel_launch(void* const* d_in, const int* in_sizes, int n_in,
                              void* d_out, int out_size) {
    const float* x    = (const float*)d_in[0];   // [8192, 1024] f32
    const float* rng  = (const float*)d_in[1];   // scalar f32
    const float* coef = (const float*)d_in[2];   // [1024, 1024, 8] f32
    float* out        = (float*)d_out;           // [8192, 1024] f32

    (void)in_sizes; (void)n_in; (void)out_size;

    // 1) prep A-tile images (tanh + powers, fp16, swizzled)
    {
        dim3 grid(NKT, NBM);   // (256, 64)
        prep_a_kernel<<<grid, 512>>>(x, rng);
    }
    // 2) prep B-tile images (coef -> fp16 k-paired, swizzled)
    {
        dim3 grid(NKT, NBN);   // (256, 8)
        prep_b_kernel<<<grid, 512>>>(coef);
    }
    // 3) split-K=4 pipelined fp16 tensor-core GEMM (R9 pipeline per split)
    {
        dim3 grid(NBN, NBM, KSPLIT);   // (8, 64, 4) = 2048 CTAs
        taylor_pipe_kernel<<<grid, 128>>>();
    }
    // 4) reduce the 4 partials into out
    {
        int threads = 256;
        int blocks = (N_F4 + threads - 1) / threads;   // 8192
        reduce_kernel<<<blocks, threads>>>(out);
    }
}